// round 12
// baseline (speedup 1.0000x reference)
#include <cuda_runtime.h>
#include <cuda_fp16.h>
#include <math.h>
#include <stdint.h>

#define D_MODEL 1024
#define B_SZ    8
#define S_LEN   2048
#define ROWS    (B_SZ * S_LEN)   /* 16384 */

// ---------------- scratch (device globals) ----------------
__device__ __half g_h16[(size_t)ROWS * D_MODEL];
__device__ __half g_qkv16[(size_t)ROWS * 3 * D_MODEL];
__device__ __half g_sc16[(size_t)B_SZ * S_LEN * S_LEN];
__device__ __half g_x2h[(size_t)ROWS * D_MODEL];
__device__ __half g_fc16[(size_t)ROWS * 4 * D_MODEL];
__device__ __half g_waT16[(size_t)3072 * 1024];
__device__ __half g_wfT16[(size_t)4096 * 1024];
__device__ __half g_wpT16[(size_t)1024 * 4096];

// ---------------- helpers ----------------
__device__ __forceinline__ float gelu_exact(float x) {
    return 0.5f * x * (1.0f + erff(x * 0.70710678118654752f));
}
__device__ __forceinline__ float warp_sum(float v) {
    #pragma unroll
    for (int o = 16; o; o >>= 1) v += __shfl_xor_sync(0xffffffffu, v, o);
    return v;
}
__device__ __forceinline__ float warp_max(float v) {
    #pragma unroll
    for (int o = 16; o; o >>= 1) v = fmaxf(v, __shfl_xor_sync(0xffffffffu, v, o));
    return v;
}
__device__ __forceinline__ void cp16(uint32_t dst_smem, const void* gptr) {
    asm volatile("cp.async.ca.shared.global [%0], [%1], 16;"
                 :: "r"(dst_smem), "l"(gptr) : "memory");
}

// ---------------- LayerNorm, warp-per-row: (fp32|fp16) in, fp16 out -------
// 256 thr = 8 warps = 8 rows per block. Lane holds 32 elements (2x16).
template <typename TI>
__global__ void ln_kernel(const TI* __restrict__ x, const float* __restrict__ w,
                          const float* __restrict__ b, __half* __restrict__ out) {
    const int lane = threadIdx.x & 31;
    const size_t row = (size_t)blockIdx.x * 8 + (threadIdx.x >> 5);

    float f[32];
    if (sizeof(TI) == 4) {
        const float* xp = (const float*)x + row * D_MODEL;
        #pragma unroll
        for (int i = 0; i < 2; i++) {
            int base = lane * 16 + i * 512;
            #pragma unroll
            for (int j = 0; j < 4; j++) {
                float4 v = *(const float4*)(xp + base + j * 4);
                f[i * 16 + j * 4 + 0] = v.x; f[i * 16 + j * 4 + 1] = v.y;
                f[i * 16 + j * 4 + 2] = v.z; f[i * 16 + j * 4 + 3] = v.w;
            }
        }
    } else {
        const __half* xp = (const __half*)x + row * D_MODEL;
        #pragma unroll
        for (int i = 0; i < 2; i++) {
            int base = lane * 16 + i * 512;
            #pragma unroll
            for (int j = 0; j < 2; j++) {
                uint4 raw = *(const uint4*)(xp + base + j * 8);
                const __half2* hp = (const __half2*)&raw;
                #pragma unroll
                for (int l = 0; l < 4; l++) {
                    float2 t = __half22float2(hp[l]);
                    f[i * 16 + j * 8 + l * 2] = t.x;
                    f[i * 16 + j * 8 + l * 2 + 1] = t.y;
                }
            }
        }
    }

    float s = 0.0f, ss = 0.0f;
    #pragma unroll
    for (int i = 0; i < 32; i++) { s += f[i]; ss += f[i] * f[i]; }
    s  = warp_sum(s);
    ss = warp_sum(ss);
    float mu  = s * (1.0f / D_MODEL);
    float var = ss * (1.0f / D_MODEL) - mu * mu;
    float inv = rsqrtf(var + 1e-5f);

    __half* op = out + row * D_MODEL;
    #pragma unroll
    for (int i = 0; i < 2; i++) {
        int base = lane * 16 + i * 512;
        uint4 st[1];
        #pragma unroll
        for (int half16 = 0; half16 < 2; half16++) {
            __half2* hp = (__half2*)&st[0];
            #pragma unroll
            for (int l = 0; l < 4; l++) {
                int idx = half16 * 8 + l * 2;
                float2 wv = *(const float2*)(w + base + idx);
                float2 bv = *(const float2*)(b + base + idx);
                hp[l] = __floats2half2_rn(
                    (f[i * 16 + idx] - mu) * inv * wv.x + bv.x,
                    (f[i * 16 + idx + 1] - mu) * inv * wv.y + bv.y);
            }
            *(uint4*)(op + base + half16 * 8) = st[0];
        }
    }
}

// ---------------- Softmax, warp-per-row over fp16 row of 2048, in-place ---
// 256 thr = 8 warps = 8 rows per block. Lane holds 64 halves (8x uint4 = full
// row: 32 lanes * 8 uint4 * 8 halves = 2048).
__global__ void softmax_kernel(__half* __restrict__ sc) {
    const int lane = threadIdx.x & 31;
    const size_t row = (size_t)blockIdx.x * 8 + (threadIdx.x >> 5);
    __half* p = sc + row * (size_t)S_LEN;

    uint4 raw[8];
    float f[64];
    #pragma unroll
    for (int i = 0; i < 8; i++) {
        raw[i] = ((uint4*)p)[lane + i * 32];
        const __half2* hp = (const __half2*)&raw[i];
        #pragma unroll
        for (int l = 0; l < 4; l++) {
            float2 t = __half22float2(hp[l]);
            f[i * 8 + l * 2] = t.x; f[i * 8 + l * 2 + 1] = t.y;
        }
    }
    float m = f[0];
    #pragma unroll
    for (int i = 1; i < 64; i++) m = fmaxf(m, f[i]);
    m = warp_max(m);
    float s = 0.0f;
    #pragma unroll
    for (int i = 0; i < 64; i++) { f[i] = expf(f[i] - m); s += f[i]; }
    s = warp_sum(s);
    float inv = 1.0f / s;
    #pragma unroll
    for (int i = 0; i < 8; i++) {
        __half2* hp = (__half2*)&raw[i];
        #pragma unroll
        for (int l = 0; l < 4; l++)
            hp[l] = __floats2half2_rn(f[i * 8 + l * 2] * inv,
                                      f[i * 8 + l * 2 + 1] * inv);
        ((uint4*)p)[lane + i * 32] = raw[i];
    }
}

// ---------------- transpose: dst[c][r] = (TO)src[r][c] ----------------
template <typename TI, typename TO>
__global__ void transpose_kernel(const TI* __restrict__ src, TO* __restrict__ dst,
                                 int lds, int ldd) {
    __shared__ float t[32][33];
    int bx = blockIdx.x * 32;
    int by = blockIdx.y * 32;
    int tx = threadIdx.x, ty = threadIdx.y;
    #pragma unroll
    for (int i = 0; i < 4; i++)
        t[ty + i * 8][tx] = (float)src[(size_t)(by + ty + i * 8) * lds + bx + tx];
    __syncthreads();
    #pragma unroll
    for (int i = 0; i < 4; i++)
        dst[(size_t)(bx + ty + i * 8) * ldd + by + tx] = (TO)t[tx][ty + i * 8];
}

// =================== fp16 mma.sync GEMM, 128x128x32, 3-stage, occ 2 ========
// C = act(alpha * A @ op(B) + bias) (+ residual)
// A [M,K] fp16 row-major.
// TRANSB=0: B [N,K] row-major (K-major), normal ldmatrix.
// TRANSB=1: B [K,N] row-major (N-major), ldmatrix.trans (e.g. V in qkv).
#define LDH 40                         /* A: 32 + 8 pad halves; 80 B stride */
#define LDBT 136                       /* trans-B: 128 + 8 pad; 272 B stride */
#define NSTAGE 3
#define A_BYTES (128 * LDH * 2)        /* 10240 */
#define BN_BYTES (128 * LDH * 2)       /* 10240: [n][k] */
#define BT_BYTES (32 * LDBT * 2)       /* 8704:  [k][n] */

template <bool TRANSB, bool BIAS, int ACT, bool RES, bool OUT16>
__global__ __launch_bounds__(256, 2)
void hgemm(const __half* __restrict__ A, const __half* __restrict__ B,
           const float* __restrict__ bias, const float* __restrict__ res,
           void* __restrict__ Cv,
           int K, int lda, int ldb, int ldc, int ldres,
           size_t sA, size_t sB, size_t sC, size_t sR, float alpha) {
    constexpr int B_BYTES = TRANSB ? BT_BYTES : BN_BYTES;
    constexpr int STAGE_BYTES = A_BYTES + B_BYTES;

    extern __shared__ char dsm[];
    const uint32_t sbase = (uint32_t)__cvta_generic_to_shared(dsm);

    const int bn = blockIdx.x, bm = blockIdx.y, bz = blockIdx.z;
    const __half* Ab = A + sA * bz + (size_t)bm * 128 * lda;
    const __half* Bb = TRANSB ? (B + sB * bz + (size_t)bn * 128)
                              : (B + sB * bz + (size_t)bn * 128 * ldb);

    const int tid  = threadIdx.x;
    const int lane = tid & 31;
    const int warp = tid >> 5;
    const int wm   = warp >> 1;
    const int wn   = warp & 1;

    const uint32_t a_off = (uint32_t)((lane & 15) * 80 + (lane >> 4) * 16);
    const uint32_t bn_row = (uint32_t)(((lane >> 4) << 3) + (lane & 7));
    const uint32_t bn_off = (uint32_t)(bn_row * 80 + ((lane >> 3) & 1) * 16);
    const uint32_t bt_off = (uint32_t)((lane & 15) * 272 + (lane >> 4) * 16);

    float acc[2][8][4];
    #pragma unroll
    for (int i = 0; i < 2; i++)
        #pragma unroll
        for (int j = 0; j < 8; j++)
            #pragma unroll
            for (int l = 0; l < 4; l++) acc[i][j][l] = 0.0f;

    const int T = K >> 5;

    auto stage = [&](int kt, int s) {
        const int k0 = kt << 5;
        const uint32_t sa = sbase + s * STAGE_BYTES;
        const uint32_t sb = sa + A_BYTES;
        const __half* gA = Ab + (size_t)(tid >> 1) * lda + k0 + (tid & 1) * 16;
        const uint32_t dA = sa + (tid >> 1) * 80 + (tid & 1) * 32;
        cp16(dA, gA);
        cp16(dA + 16, gA + 8);
        if (TRANSB) {
            const int kr = tid >> 3;
            const __half* gB = Bb + (size_t)(k0 + kr) * ldb + (tid & 7) * 16;
            const uint32_t dB = sb + kr * 272 + (tid & 7) * 32;
            cp16(dB, gB);
            cp16(dB + 16, gB + 8);
        } else {
            const __half* gB = Bb + (size_t)(tid >> 1) * ldb + k0 + (tid & 1) * 16;
            const uint32_t dB = sb + (tid >> 1) * 80 + (tid & 1) * 32;
            cp16(dB, gB);
            cp16(dB + 16, gB + 8);
        }
    };

    #pragma unroll
    for (int s = 0; s < NSTAGE; s++) {
        if (s < T) stage(s, s);
        asm volatile("cp.async.commit_group;" ::: "memory");
    }

    int buf = 0;
    for (int kt = 0; kt < T; kt++) {
        asm volatile("cp.async.wait_group %0;" :: "n"(NSTAGE - 1) : "memory");
        __syncthreads();

        const uint32_t sa = sbase + buf * STAGE_BYTES;
        const uint32_t sb = sa + A_BYTES;

        #pragma unroll
        for (int ks = 0; ks < 2; ks++) {
            uint32_t a[2][4];
            #pragma unroll
            for (int am = 0; am < 2; am++) {
                uint32_t addr = sa + (uint32_t)((wm * 32 + am * 16) * 80)
                              + a_off + ks * 32;
                asm volatile(
                    "ldmatrix.sync.aligned.m8n8.x4.shared.b16 {%0,%1,%2,%3}, [%4];"
                    : "=r"(a[am][0]), "=r"(a[am][1]), "=r"(a[am][2]), "=r"(a[am][3])
                    : "r"(addr));
            }
            uint32_t b[8][2];
            #pragma unroll
            for (int t = 0; t < 4; t++) {
                uint32_t r0, r1, r2, r3;
                if (TRANSB) {
                    uint32_t addr = sb + (uint32_t)(ks * 16 * 272)
                                  + (uint32_t)((wn * 64 + t * 16) * 2) + bt_off;
                    asm volatile(
                        "ldmatrix.sync.aligned.m8n8.x4.trans.shared.b16 {%0,%1,%2,%3}, [%4];"
                        : "=r"(r0), "=r"(r1), "=r"(r2), "=r"(r3)
                        : "r"(addr));
                } else {
                    uint32_t addr = sb + (uint32_t)((wn * 64 + t * 16) * 80)
                                  + bn_off + ks * 32;
                    asm volatile(
                        "ldmatrix.sync.aligned.m8n8.x4.shared.b16 {%0,%1,%2,%3}, [%4];"
                        : "=r"(r0), "=r"(r1), "=r"(r2), "=r"(r3)
                        : "r"(addr));
                }
                b[2 * t][0] = r0; b[2 * t][1] = r1;
                b[2 * t + 1][0] = r2; b[2 * t + 1][1] = r3;
            }
            #pragma unroll
            for (int am = 0; am < 2; am++)
                #pragma unroll
                for (int an = 0; an < 8; an++) {
                    asm volatile(
                        "mma.sync.aligned.m16n8k16.row.col.f32.f16.f16.f32 "
                        "{%0,%1,%2,%3}, {%4,%5,%6,%7}, {%8,%9}, {%0,%1,%2,%3};"
                        : "+f"(acc[am][an][0]), "+f"(acc[am][an][1]),
                          "+f"(acc[am][an][2]), "+f"(acc[am][an][3])
                        : "r"(a[am][0]), "r"(a[am][1]), "r"(a[am][2]), "r"(a[am][3]),
                          "r"(b[an][0]), "r"(b[an][1]));
                }
        }
        __syncthreads();
        if (kt + NSTAGE < T) stage(kt + NSTAGE, buf);
        asm volatile("cp.async.commit_group;" ::: "memory");
        buf = (buf + 1 == NSTAGE) ? 0 : buf + 1;
    }

    // ---- epilogue ----
    const int q  = lane >> 2;
    const int r2 = (lane & 3) * 2;
    #pragma unroll
    for (int am = 0; am < 2; am++) {
        int row0 = bm * 128 + wm * 32 + am * 16 + q;
        int row1 = row0 + 8;
        #pragma unroll
        for (int an = 0; an < 8; an++) {
            int col = bn * 128 + wn * 64 + an * 8 + r2;
            float v00 = acc[am][an][0] * alpha;
            float v01 = acc[am][an][1] * alpha;
            float v10 = acc[am][an][2] * alpha;
            float v11 = acc[am][an][3] * alpha;
            if (BIAS) {
                float2 bv = *(const float2*)(bias + col);
                v00 += bv.x; v01 += bv.y; v10 += bv.x; v11 += bv.y;
            }
            if (ACT == 1) {
                v00 = gelu_exact(v00); v01 = gelu_exact(v01);
                v10 = gelu_exact(v10); v11 = gelu_exact(v11);
            }
            if (RES) {
                float2 r0 = *(const float2*)(res + sR * bz + (size_t)row0 * ldres + col);
                float2 r1 = *(const float2*)(res + sR * bz + (size_t)row1 * ldres + col);
                v00 += r0.x; v01 += r0.y; v10 += r1.x; v11 += r1.y;
            }
            if (OUT16) {
                __half* Cb = (__half*)Cv + sC * bz;
                *(__half2*)(Cb + (size_t)row0 * ldc + col) = __floats2half2_rn(v00, v01);
                *(__half2*)(Cb + (size_t)row1 * ldc + col) = __floats2half2_rn(v10, v11);
            } else {
                float* Cb = (float*)Cv + sC * bz;
                *(float2*)(Cb + (size_t)row0 * ldc + col) = make_float2(v00, v01);
                *(float2*)(Cb + (size_t)row1 * ldc + col) = make_float2(v10, v11);
            }
        }
    }
}

#define GSMEM_N (NSTAGE * (A_BYTES + BN_BYTES))   /* 61440 */
#define GSMEM_T (NSTAGE * (A_BYTES + BT_BYTES))   /* 56832 */

// ---------------- launch ----------------
extern "C" void kernel_launch(void* const* d_in, const int* in_sizes, int n_in,
                              void* d_out, int out_size) {
    const float* x      = (const float*)d_in[0];
    const float* ln1_w  = (const float*)d_in[1];
    const float* ln1_b  = (const float*)d_in[2];
    const float* W_attn = (const float*)d_in[3];
    const float* b_attn = (const float*)d_in[4];
    const float* ln2_w  = (const float*)d_in[5];
    const float* ln2_b  = (const float*)d_in[6];
    const float* W_fc   = (const float*)d_in[7];
    const float* b_fc   = (const float*)d_in[8];
    const float* W_proj = (const float*)d_in[9];
    const float* b_proj = (const float*)d_in[10];
    float* out = (float*)d_out;

    void* p;
    cudaGetSymbolAddress(&p, g_h16);    __half* h    = (__half*)p;
    cudaGetSymbolAddress(&p, g_qkv16);  __half* qkv  = (__half*)p;
    cudaGetSymbolAddress(&p, g_sc16);   __half* sc   = (__half*)p;
    cudaGetSymbolAddress(&p, g_x2h);    __half* x2   = (__half*)p;
    cudaGetSymbolAddress(&p, g_fc16);   __half* fcb  = (__half*)p;
    cudaGetSymbolAddress(&p, g_waT16);  __half* waT  = (__half*)p;
    cudaGetSymbolAddress(&p, g_wfT16);  __half* wfT  = (__half*)p;
    cudaGetSymbolAddress(&p, g_wpT16);  __half* wpT  = (__half*)p;

    cudaFuncSetAttribute(hgemm<false, true, 0, false, true>,
                         cudaFuncAttributeMaxDynamicSharedMemorySize, GSMEM_N);
    cudaFuncSetAttribute(hgemm<false, false, 0, false, true>,
                         cudaFuncAttributeMaxDynamicSharedMemorySize, GSMEM_N);
    cudaFuncSetAttribute(hgemm<true, false, 0, true, true>,
                         cudaFuncAttributeMaxDynamicSharedMemorySize, GSMEM_T);
    cudaFuncSetAttribute(hgemm<false, true, 1, false, true>,
                         cudaFuncAttributeMaxDynamicSharedMemorySize, GSMEM_N);
    cudaFuncSetAttribute(hgemm<false, true, 0, false, false>,
                         cudaFuncAttributeMaxDynamicSharedMemorySize, GSMEM_N);

    dim3 blk(256);
    dim3 tblk(32, 8);

    // weight transposes -> K-major fp16
    transpose_kernel<float, __half><<<dim3(96, 32), tblk>>>(W_attn, waT, 3072, 1024);
    transpose_kernel<float, __half><<<dim3(128, 32), tblk>>>(W_fc, wfT, 4096, 1024);
    transpose_kernel<float, __half><<<dim3(32, 128), tblk>>>(W_proj, wpT, 1024, 4096);

    // 1) h = LN1(x) -> fp16  (warp-per-row)
    ln_kernel<float><<<ROWS / 8, blk>>>(x, ln1_w, ln1_b, h);

    // 2) qkv = h @ W_attn + b_attn -> fp16 [16384,3072]
    hgemm<false, true, 0, false, true><<<dim3(24, 128, 1), blk, GSMEM_N>>>(
        h, waT, b_attn, nullptr, qkv,
        1024, 1024, 1024, 3072, 0, 0, 0, 0, 0, 1.0f);

    // 3) scores = (q @ k^T)/sqrt(D) -> fp16
    hgemm<false, false, 0, false, true><<<dim3(16, 16, 8), blk, GSMEM_N>>>(
        qkv, qkv + 1024, nullptr, nullptr, sc,
        1024, 3072, 3072, 2048, 0,
        (size_t)S_LEN * 3072, (size_t)S_LEN * 3072, (size_t)S_LEN * S_LEN, 0,
        0.03125f);

    // 4) softmax (warp-per-row, full 2048-row coverage, fp16 in/out)
    softmax_kernel<<<ROWS / 8, blk>>>(sc);

    // 5) x2 = x + attn @ V -> fp16  (trans-B: V = qkv[:, 2048:] as [K,N])
    hgemm<true, false, 0, true, true><<<dim3(8, 16, 8), blk, GSMEM_T>>>(
        sc, qkv + 2048, nullptr, x, x2,
        2048, 2048, 3072, 1024, 1024,
        (size_t)S_LEN * S_LEN, (size_t)S_LEN * 3072,
        (size_t)S_LEN * 1024, (size_t)S_LEN * 1024, 1.0f);

    // 6) h = LN2(x2) -> fp16  (warp-per-row, fp16 input)
    ln_kernel<__half><<<ROWS / 8, blk>>>(x2, ln2_w, ln2_b, h);

    // 7) fc = gelu(h @ W_fc + b_fc) -> fp16 [16384,4096]
    hgemm<false, true, 1, false, true><<<dim3(32, 128, 1), blk, GSMEM_N>>>(
        h, wfT, b_fc, nullptr, fcb,
        1024, 1024, 1024, 4096, 0, 0, 0, 0, 0, 1.0f);

    // 8) out = fc @ W_proj + b_proj -> fp32 [16384,1024]
    hgemm<false, true, 0, false, false><<<dim3(8, 128, 1), blk, GSMEM_N>>>(
        fcb, wpT, b_proj, nullptr, out,
        4096, 4096, 4096, 1024, 0, 0, 0, 0, 0, 1.0f);
}

// round 13
// speedup vs baseline: 1.0192x; 1.0192x over previous
#include <cuda_runtime.h>
#include <cuda_fp16.h>
#include <math.h>
#include <stdint.h>

#define D_MODEL 1024
#define B_SZ    8
#define S_LEN   2048
#define ROWS    (B_SZ * S_LEN)   /* 16384 */

// ---------------- scratch (device globals) ----------------
__device__ __half g_h16[(size_t)ROWS * D_MODEL];
__device__ __half g_qkv16[(size_t)ROWS * 3 * D_MODEL];
__device__ __half g_sc16[(size_t)B_SZ * S_LEN * S_LEN];
__device__ __half g_x2h[(size_t)ROWS * D_MODEL];
__device__ __half g_fc16[(size_t)ROWS * 4 * D_MODEL];
__device__ __half g_waT16[(size_t)3072 * 1024];
__device__ __half g_wfT16[(size_t)4096 * 1024];
__device__ __half g_wpT16[(size_t)1024 * 4096];

// ---------------- helpers ----------------
__device__ __forceinline__ float gelu_exact(float x) {
    return 0.5f * x * (1.0f + erff(x * 0.70710678118654752f));
}
__device__ __forceinline__ float warp_sum(float v) {
    #pragma unroll
    for (int o = 16; o; o >>= 1) v += __shfl_xor_sync(0xffffffffu, v, o);
    return v;
}
__device__ __forceinline__ float warp_max(float v) {
    #pragma unroll
    for (int o = 16; o; o >>= 1) v = fmaxf(v, __shfl_xor_sync(0xffffffffu, v, o));
    return v;
}
__device__ __forceinline__ void cp16(uint32_t dst_smem, const void* gptr) {
    asm volatile("cp.async.ca.shared.global [%0], [%1], 16;"
                 :: "r"(dst_smem), "l"(gptr) : "memory");
}

// ---------------- LayerNorm, warp-per-row, coalesced ----------------
// 256 thr = 8 warps = 8 rows per block. No block barriers.
// fp32 in: lane owns cols lane*4 + j*128 (j<8), float4 loads (coalesced).
// fp16 in: lane owns cols lane*8 + j*256 (j<4), uint4 loads (coalesced).
template <typename TI>
__global__ void ln_kernel(const TI* __restrict__ x, const float* __restrict__ w,
                          const float* __restrict__ b, __half* __restrict__ out) {
    const int lane = threadIdx.x & 31;
    const size_t row = (size_t)blockIdx.x * 8 + (threadIdx.x >> 5);
    __half* op = out + row * D_MODEL;

    float f[32];
    if (sizeof(TI) == 4) {
        const float* xp = (const float*)x + row * D_MODEL;
        #pragma unroll
        for (int j = 0; j < 8; j++) {
            float4 v = *(const float4*)(xp + lane * 4 + j * 128);
            f[j * 4 + 0] = v.x; f[j * 4 + 1] = v.y;
            f[j * 4 + 2] = v.z; f[j * 4 + 3] = v.w;
        }
    } else {
        const __half* xp = (const __half*)x + row * D_MODEL;
        #pragma unroll
        for (int j = 0; j < 4; j++) {
            uint4 raw = *(const uint4*)(xp + lane * 8 + j * 256);
            const __half2* hp = (const __half2*)&raw;
            #pragma unroll
            for (int l = 0; l < 4; l++) {
                float2 t = __half22float2(hp[l]);
                f[j * 8 + l * 2] = t.x; f[j * 8 + l * 2 + 1] = t.y;
            }
        }
    }

    float s = 0.0f, ss = 0.0f;
    #pragma unroll
    for (int i = 0; i < 32; i++) { s += f[i]; ss += f[i] * f[i]; }
    s  = warp_sum(s);
    ss = warp_sum(ss);
    float mu  = s * (1.0f / D_MODEL);
    float var = ss * (1.0f / D_MODEL) - mu * mu;
    float inv = rsqrtf(var + 1e-5f);

    if (sizeof(TI) == 4) {
        #pragma unroll
        for (int j = 0; j < 8; j++) {
            int base = lane * 4 + j * 128;
            float4 wv = *(const float4*)(w + base);
            float4 bv = *(const float4*)(b + base);
            uint2 st;
            __half2* hp = (__half2*)&st;
            hp[0] = __floats2half2_rn((f[j * 4 + 0] - mu) * inv * wv.x + bv.x,
                                      (f[j * 4 + 1] - mu) * inv * wv.y + bv.y);
            hp[1] = __floats2half2_rn((f[j * 4 + 2] - mu) * inv * wv.z + bv.z,
                                      (f[j * 4 + 3] - mu) * inv * wv.w + bv.w);
            *(uint2*)(op + base) = st;
        }
    } else {
        #pragma unroll
        for (int j = 0; j < 4; j++) {
            int base = lane * 8 + j * 256;
            uint4 st;
            __half2* hp = (__half2*)&st;
            #pragma unroll
            for (int l = 0; l < 4; l++) {
                float2 wv = *(const float2*)(w + base + l * 2);
                float2 bv = *(const float2*)(b + base + l * 2);
                hp[l] = __floats2half2_rn(
                    (f[j * 8 + l * 2] - mu) * inv * wv.x + bv.x,
                    (f[j * 8 + l * 2 + 1] - mu) * inv * wv.y + bv.y);
            }
            *(uint4*)(op + base) = st;
        }
    }
}

// ---------------- Softmax, warp-per-row over fp16 row of 2048, in-place ---
// 256 thr = 8 warps = 8 rows. Lane owns 8 uint4 at lane + i*32 (coalesced).
__global__ void softmax_kernel(__half* __restrict__ sc) {
    const int lane = threadIdx.x & 31;
    const size_t row = (size_t)blockIdx.x * 8 + (threadIdx.x >> 5);
    __half* p = sc + row * (size_t)S_LEN;

    uint4 raw[8];
    float f[64];
    #pragma unroll
    for (int i = 0; i < 8; i++) {
        raw[i] = ((uint4*)p)[lane + i * 32];
        const __half2* hp = (const __half2*)&raw[i];
        #pragma unroll
        for (int l = 0; l < 4; l++) {
            float2 t = __half22float2(hp[l]);
            f[i * 8 + l * 2] = t.x; f[i * 8 + l * 2 + 1] = t.y;
        }
    }
    float m = f[0];
    #pragma unroll
    for (int i = 1; i < 64; i++) m = fmaxf(m, f[i]);
    m = warp_max(m);
    float s = 0.0f;
    #pragma unroll
    for (int i = 0; i < 64; i++) { f[i] = expf(f[i] - m); s += f[i]; }
    s = warp_sum(s);
    float inv = 1.0f / s;
    #pragma unroll
    for (int i = 0; i < 8; i++) {
        __half2* hp = (__half2*)&raw[i];
        #pragma unroll
        for (int l = 0; l < 4; l++)
            hp[l] = __floats2half2_rn(f[i * 8 + l * 2] * inv,
                                      f[i * 8 + l * 2 + 1] * inv);
        ((uint4*)p)[lane + i * 32] = raw[i];
    }
}

// ---------------- transpose: dst[c][r] = (TO)src[r][c] ----------------
template <typename TI, typename TO>
__global__ void transpose_kernel(const TI* __restrict__ src, TO* __restrict__ dst,
                                 int lds, int ldd) {
    __shared__ float t[32][33];
    int bx = blockIdx.x * 32;
    int by = blockIdx.y * 32;
    int tx = threadIdx.x, ty = threadIdx.y;
    #pragma unroll
    for (int i = 0; i < 4; i++)
        t[ty + i * 8][tx] = (float)src[(size_t)(by + ty + i * 8) * lds + bx + tx];
    __syncthreads();
    #pragma unroll
    for (int i = 0; i < 4; i++)
        dst[(size_t)(bx + ty + i * 8) * ldd + by + tx] = (TO)t[tx][ty + i * 8];
}

// =================== fp16 mma.sync GEMM, 128x128x32, 3-stage, occ 2 ========
// C = act(alpha * A @ op(B) + bias) (+ residual)
// A [M,K] fp16 row-major.
// TRANSB=0: B [N,K] row-major (K-major), normal ldmatrix.
// TRANSB=1: B [K,N] row-major (N-major), ldmatrix.trans (e.g. V in qkv).
#define LDH 40                         /* A: 32 + 8 pad halves; 80 B stride */
#define LDBT 136                       /* trans-B: 128 + 8 pad; 272 B stride */
#define NSTAGE 3
#define A_BYTES (128 * LDH * 2)        /* 10240 */
#define BN_BYTES (128 * LDH * 2)       /* 10240: [n][k] */
#define BT_BYTES (32 * LDBT * 2)       /* 8704:  [k][n] */

template <bool TRANSB, bool BIAS, int ACT, bool RES, bool OUT16>
__global__ __launch_bounds__(256, 2)
void hgemm(const __half* __restrict__ A, const __half* __restrict__ B,
           const float* __restrict__ bias, const float* __restrict__ res,
           void* __restrict__ Cv,
           int K, int lda, int ldb, int ldc, int ldres,
           size_t sA, size_t sB, size_t sC, size_t sR, float alpha) {
    constexpr int B_BYTES = TRANSB ? BT_BYTES : BN_BYTES;
    constexpr int STAGE_BYTES = A_BYTES + B_BYTES;

    extern __shared__ char dsm[];
    const uint32_t sbase = (uint32_t)__cvta_generic_to_shared(dsm);

    const int bn = blockIdx.x, bm = blockIdx.y, bz = blockIdx.z;
    const __half* Ab = A + sA * bz + (size_t)bm * 128 * lda;
    const __half* Bb = TRANSB ? (B + sB * bz + (size_t)bn * 128)
                              : (B + sB * bz + (size_t)bn * 128 * ldb);

    const int tid  = threadIdx.x;
    const int lane = tid & 31;
    const int warp = tid >> 5;
    const int wm   = warp >> 1;
    const int wn   = warp & 1;

    const uint32_t a_off = (uint32_t)((lane & 15) * 80 + (lane >> 4) * 16);
    const uint32_t bn_row = (uint32_t)(((lane >> 4) << 3) + (lane & 7));
    const uint32_t bn_off = (uint32_t)(bn_row * 80 + ((lane >> 3) & 1) * 16);
    const uint32_t bt_off = (uint32_t)((lane & 15) * 272 + (lane >> 4) * 16);

    float acc[2][8][4];
    #pragma unroll
    for (int i = 0; i < 2; i++)
        #pragma unroll
        for (int j = 0; j < 8; j++)
            #pragma unroll
            for (int l = 0; l < 4; l++) acc[i][j][l] = 0.0f;

    const int T = K >> 5;

    auto stage = [&](int kt, int s) {
        const int k0 = kt << 5;
        const uint32_t sa = sbase + s * STAGE_BYTES;
        const uint32_t sb = sa + A_BYTES;
        const __half* gA = Ab + (size_t)(tid >> 1) * lda + k0 + (tid & 1) * 16;
        const uint32_t dA = sa + (tid >> 1) * 80 + (tid & 1) * 32;
        cp16(dA, gA);
        cp16(dA + 16, gA + 8);
        if (TRANSB) {
            const int kr = tid >> 3;
            const __half* gB = Bb + (size_t)(k0 + kr) * ldb + (tid & 7) * 16;
            const uint32_t dB = sb + kr * 272 + (tid & 7) * 32;
            cp16(dB, gB);
            cp16(dB + 16, gB + 8);
        } else {
            const __half* gB = Bb + (size_t)(tid >> 1) * ldb + k0 + (tid & 1) * 16;
            const uint32_t dB = sb + (tid >> 1) * 80 + (tid & 1) * 32;
            cp16(dB, gB);
            cp16(dB + 16, gB + 8);
        }
    };

    #pragma unroll
    for (int s = 0; s < NSTAGE; s++) {
        if (s < T) stage(s, s);
        asm volatile("cp.async.commit_group;" ::: "memory");
    }

    int buf = 0;
    for (int kt = 0; kt < T; kt++) {
        asm volatile("cp.async.wait_group %0;" :: "n"(NSTAGE - 1) : "memory");
        __syncthreads();

        const uint32_t sa = sbase + buf * STAGE_BYTES;
        const uint32_t sb = sa + A_BYTES;

        #pragma unroll
        for (int ks = 0; ks < 2; ks++) {
            uint32_t a[2][4];
            #pragma unroll
            for (int am = 0; am < 2; am++) {
                uint32_t addr = sa + (uint32_t)((wm * 32 + am * 16) * 80)
                              + a_off + ks * 32;
                asm volatile(
                    "ldmatrix.sync.aligned.m8n8.x4.shared.b16 {%0,%1,%2,%3}, [%4];"
                    : "=r"(a[am][0]), "=r"(a[am][1]), "=r"(a[am][2]), "=r"(a[am][3])
                    : "r"(addr));
            }
            uint32_t b[8][2];
            #pragma unroll
            for (int t = 0; t < 4; t++) {
                uint32_t r0, r1, r2, r3;
                if (TRANSB) {
                    uint32_t addr = sb + (uint32_t)(ks * 16 * 272)
                                  + (uint32_t)((wn * 64 + t * 16) * 2) + bt_off;
                    asm volatile(
                        "ldmatrix.sync.aligned.m8n8.x4.trans.shared.b16 {%0,%1,%2,%3}, [%4];"
                        : "=r"(r0), "=r"(r1), "=r"(r2), "=r"(r3)
                        : "r"(addr));
                } else {
                    uint32_t addr = sb + (uint32_t)((wn * 64 + t * 16) * 80)
                                  + bn_off + ks * 32;
                    asm volatile(
                        "ldmatrix.sync.aligned.m8n8.x4.shared.b16 {%0,%1,%2,%3}, [%4];"
                        : "=r"(r0), "=r"(r1), "=r"(r2), "=r"(r3)
                        : "r"(addr));
                }
                b[2 * t][0] = r0; b[2 * t][1] = r1;
                b[2 * t + 1][0] = r2; b[2 * t + 1][1] = r3;
            }
            #pragma unroll
            for (int am = 0; am < 2; am++)
                #pragma unroll
                for (int an = 0; an < 8; an++) {
                    asm volatile(
                        "mma.sync.aligned.m16n8k16.row.col.f32.f16.f16.f32 "
                        "{%0,%1,%2,%3}, {%4,%5,%6,%7}, {%8,%9}, {%0,%1,%2,%3};"
                        : "+f"(acc[am][an][0]), "+f"(acc[am][an][1]),
                          "+f"(acc[am][an][2]), "+f"(acc[am][an][3])
                        : "r"(a[am][0]), "r"(a[am][1]), "r"(a[am][2]), "r"(a[am][3]),
                          "r"(b[an][0]), "r"(b[an][1]));
                }
        }
        __syncthreads();
        if (kt + NSTAGE < T) stage(kt + NSTAGE, buf);
        asm volatile("cp.async.commit_group;" ::: "memory");
        buf = (buf + 1 == NSTAGE) ? 0 : buf + 1;
    }

    // ---- epilogue ----
    const int q  = lane >> 2;
    const int r2 = (lane & 3) * 2;
    #pragma unroll
    for (int am = 0; am < 2; am++) {
        int row0 = bm * 128 + wm * 32 + am * 16 + q;
        int row1 = row0 + 8;
        #pragma unroll
        for (int an = 0; an < 8; an++) {
            int col = bn * 128 + wn * 64 + an * 8 + r2;
            float v00 = acc[am][an][0] * alpha;
            float v01 = acc[am][an][1] * alpha;
            float v10 = acc[am][an][2] * alpha;
            float v11 = acc[am][an][3] * alpha;
            if (BIAS) {
                float2 bv = *(const float2*)(bias + col);
                v00 += bv.x; v01 += bv.y; v10 += bv.x; v11 += bv.y;
            }
            if (ACT == 1) {
                v00 = gelu_exact(v00); v01 = gelu_exact(v01);
                v10 = gelu_exact(v10); v11 = gelu_exact(v11);
            }
            if (RES) {
                float2 r0 = *(const float2*)(res + sR * bz + (size_t)row0 * ldres + col);
                float2 r1 = *(const float2*)(res + sR * bz + (size_t)row1 * ldres + col);
                v00 += r0.x; v01 += r0.y; v10 += r1.x; v11 += r1.y;
            }
            if (OUT16) {
                __half* Cb = (__half*)Cv + sC * bz;
                *(__half2*)(Cb + (size_t)row0 * ldc + col) = __floats2half2_rn(v00, v01);
                *(__half2*)(Cb + (size_t)row1 * ldc + col) = __floats2half2_rn(v10, v11);
            } else {
                float* Cb = (float*)Cv + sC * bz;
                *(float2*)(Cb + (size_t)row0 * ldc + col) = make_float2(v00, v01);
                *(float2*)(Cb + (size_t)row1 * ldc + col) = make_float2(v10, v11);
            }
        }
    }
}

#define GSMEM_N (NSTAGE * (A_BYTES + BN_BYTES))   /* 61440 */
#define GSMEM_T (NSTAGE * (A_BYTES + BT_BYTES))   /* 56832 */

// ---------------- launch ----------------
extern "C" void kernel_launch(void* const* d_in, const int* in_sizes, int n_in,
                              void* d_out, int out_size) {
    const float* x      = (const float*)d_in[0];
    const float* ln1_w  = (const float*)d_in[1];
    const float* ln1_b  = (const float*)d_in[2];
    const float* W_attn = (const float*)d_in[3];
    const float* b_attn = (const float*)d_in[4];
    const float* ln2_w  = (const float*)d_in[5];
    const float* ln2_b  = (const float*)d_in[6];
    const float* W_fc   = (const float*)d_in[7];
    const float* b_fc   = (const float*)d_in[8];
    const float* W_proj = (const float*)d_in[9];
    const float* b_proj = (const float*)d_in[10];
    float* out = (float*)d_out;

    void* p;
    cudaGetSymbolAddress(&p, g_h16);    __half* h    = (__half*)p;
    cudaGetSymbolAddress(&p, g_qkv16);  __half* qkv  = (__half*)p;
    cudaGetSymbolAddress(&p, g_sc16);   __half* sc   = (__half*)p;
    cudaGetSymbolAddress(&p, g_x2h);    __half* x2   = (__half*)p;
    cudaGetSymbolAddress(&p, g_fc16);   __half* fcb  = (__half*)p;
    cudaGetSymbolAddress(&p, g_waT16);  __half* waT  = (__half*)p;
    cudaGetSymbolAddress(&p, g_wfT16);  __half* wfT  = (__half*)p;
    cudaGetSymbolAddress(&p, g_wpT16);  __half* wpT  = (__half*)p;

    cudaFuncSetAttribute(hgemm<false, true, 0, false, true>,
                         cudaFuncAttributeMaxDynamicSharedMemorySize, GSMEM_N);
    cudaFuncSetAttribute(hgemm<false, false, 0, false, true>,
                         cudaFuncAttributeMaxDynamicSharedMemorySize, GSMEM_N);
    cudaFuncSetAttribute(hgemm<true, false, 0, true, true>,
                         cudaFuncAttributeMaxDynamicSharedMemorySize, GSMEM_T);
    cudaFuncSetAttribute(hgemm<false, true, 1, false, true>,
                         cudaFuncAttributeMaxDynamicSharedMemorySize, GSMEM_N);
    cudaFuncSetAttribute(hgemm<false, true, 0, false, false>,
                         cudaFuncAttributeMaxDynamicSharedMemorySize, GSMEM_N);

    dim3 blk(256);
    dim3 tblk(32, 8);

    // weight transposes -> K-major fp16
    transpose_kernel<float, __half><<<dim3(96, 32), tblk>>>(W_attn, waT, 3072, 1024);
    transpose_kernel<float, __half><<<dim3(128, 32), tblk>>>(W_fc, wfT, 4096, 1024);
    transpose_kernel<float, __half><<<dim3(32, 128), tblk>>>(W_proj, wpT, 1024, 4096);

    // 1) h = LN1(x) -> fp16  (warp-per-row, coalesced)
    ln_kernel<float><<<ROWS / 8, blk>>>(x, ln1_w, ln1_b, h);

    // 2) qkv = h @ W_attn + b_attn -> fp16 [16384,3072]
    hgemm<false, true, 0, false, true><<<dim3(24, 128, 1), blk, GSMEM_N>>>(
        h, waT, b_attn, nullptr, qkv,
        1024, 1024, 1024, 3072, 0, 0, 0, 0, 0, 1.0f);

    // 3) scores = (q @ k^T)/sqrt(D) -> fp16
    hgemm<false, false, 0, false, true><<<dim3(16, 16, 8), blk, GSMEM_N>>>(
        qkv, qkv + 1024, nullptr, nullptr, sc,
        1024, 3072, 3072, 2048, 0,
        (size_t)S_LEN * 3072, (size_t)S_LEN * 3072, (size_t)S_LEN * S_LEN, 0,
        0.03125f);

    // 4) softmax (warp-per-row, coalesced, fp16 in/out)
    softmax_kernel<<<ROWS / 8, blk>>>(sc);

    // 5) x2 = x + attn @ V -> fp16  (trans-B: V = qkv[:, 2048:] as [K,N])
    hgemm<true, false, 0, true, true><<<dim3(8, 16, 8), blk, GSMEM_T>>>(
        sc, qkv + 2048, nullptr, x, x2,
        2048, 2048, 3072, 1024, 1024,
        (size_t)S_LEN * S_LEN, (size_t)S_LEN * 3072,
        (size_t)S_LEN * 1024, (size_t)S_LEN * 1024, 1.0f);

    // 6) h = LN2(x2) -> fp16  (warp-per-row, coalesced, fp16 input)
    ln_kernel<__half><<<ROWS / 8, blk>>>(x2, ln2_w, ln2_b, h);

    // 7) fc = gelu(h @ W_fc + b_fc) -> fp16 [16384,4096]
    hgemm<false, true, 1, false, true><<<dim3(32, 128, 1), blk, GSMEM_N>>>(
        h, wfT, b_fc, nullptr, fcb,
        1024, 1024, 1024, 4096, 0, 0, 0, 0, 0, 1.0f);

    // 8) out = fc @ W_proj + b_proj -> fp32 [16384,1024]
    hgemm<false, true, 0, false, false><<<dim3(8, 128, 1), blk, GSMEM_N>>>(
        fcb, wpT, b_proj, nullptr, out,
        4096, 4096, 4096, 1024, 0, 0, 0, 0, 0, 1.0f);
}